// round 14
// baseline (speedup 1.0000x reference)
#include <cuda_runtime.h>
#include <cstdint>

#define N_POINTS   2048
#define LEVELS     16
#define TABLE_SIZE 524288
#define FEATS      8
#define OUT_COLS   (LEVELS * N_POINTS)   // 32768

#define ROWS_PER_BLOCK 64
#define COLS_PER_BLOCK 128
#define THREADS        256

__global__ __launch_bounds__(THREADS, 6)
void mrhe_kernel(const float* __restrict__ x,
                 const float* __restrict__ tables,
                 float* __restrict__ out)
{
    // out[i][j] = base[j] + fx[i]*dx[j] + fy[i]*dy[j] + fz[i]*dz[j]
    //   base = (f0+f2+f4)/3, dx = (f1-f0)/3, dy = (f3-f2)/3, dz = (f5-f4)/3
    // sB transposed: j-quad = one conflict-free LDS.128.
    // sA packed float4: one broadcast LDS.128 per row.
    __shared__ float  sB[4][COLS_PER_BLOCK];
    __shared__ float4 sA4[ROWS_PER_BLOCK];

    const int level = blockIdx.z;
    const int jt    = blockIdx.x * COLS_PER_BLOCK;
    const int it    = blockIdx.y * ROWS_PER_BLOCK;
    const float gridres = (float)(2 << level);        // 2^(level+1), exact
    const float* tab = tables + (size_t)level * TABLE_SIZE * FEATS;
    const int tid = threadIdx.x;
    const float inv3 = 1.0f / 3.0f;

    if (tid < COLS_PER_BLOCK) {
        // --- B tile: hash gather for column point j ---
        const int j = jt + tid;
        const float xj0 = x[j*3+0], xj1 = x[j*3+1], xj2 = x[j*3+2];
        const int hx = (int)floorf(xj0 * gridres);
        const int hy = (int)floorf(xj1 * gridres);
        const int hz = (int)floorf(xj2 * gridres);
        const int h  = (hx + hy + hz) & (TABLE_SIZE - 1); // sum < 2^19 == % T
        const float* row = tab + (size_t)h * FEATS;
        const float4 f03 = *(const float4*)(row);
        const float2 f45 = *(const float2*)(row + 4);
        sB[0][tid] = (f03.x + f03.z + f45.x) * inv3;
        sB[1][tid] = (f03.y - f03.x) * inv3;
        sB[2][tid] = (f03.w - f03.z) * inv3;
        sB[3][tid] = (f45.y - f45.x) * inv3;
    } else if (tid < COLS_PER_BLOCK + ROWS_PER_BLOCK) {
        // --- A tile: fract for row point i ---
        const int r = tid - COLS_PER_BLOCK;
        const int i = it + r;
        float sx = x[i*3+0] * gridres; sx -= floorf(sx);
        float sy = x[i*3+1] * gridres; sy -= floorf(sy);
        float sz = x[i*3+2] * gridres; sz -= floorf(sz);
        sA4[r] = make_float4(sx, sy, sz, 0.0f);
    }
    __syncthreads();

    const int jq = tid & 31;   // j-quad within tile (32 quads = 128 cols)
    const int r0 = tid >> 5;   // warp id = row phase (0..7)

    // 4 conflict-free LDS.128 pulls -> 16 registers of B state
    const float4 base = *(const float4*)&sB[0][jq * 4];
    const float4 dx   = *(const float4*)&sB[1][jq * 4];
    const float4 dy   = *(const float4*)&sB[2][jq * 4];
    const float4 dz   = *(const float4*)&sB[3][jq * 4];

    float* obase = out + (size_t)it * OUT_COLS
                       + (size_t)level * N_POINTS + jt + jq * 4;

#pragma unroll
    for (int rr = 0; rr < 8; rr++) {
        const int r = r0 + rr * 8;
        const float4 f = sA4[r];          // one broadcast LDS.128 per row
        float4 acc;
        acc.x = fmaf(f.z, dz.x, fmaf(f.y, dy.x, fmaf(f.x, dx.x, base.x)));
        acc.y = fmaf(f.z, dz.y, fmaf(f.y, dy.y, fmaf(f.x, dx.y, base.y)));
        acc.z = fmaf(f.z, dz.z, fmaf(f.y, dy.z, fmaf(f.x, dx.z, base.z)));
        acc.w = fmaf(f.z, dz.w, fmaf(f.y, dy.w, fmaf(f.x, dx.w, base.w)));
        // Write-once 256 MB stream: evict-first keeps table gathers L2-resident.
        __stcs((float4*)(obase + (size_t)r * OUT_COLS), acc);
    }
}

extern "C" void kernel_launch(void* const* d_in, const int* in_sizes, int n_in,
                              void* d_out, int out_size)
{
    const float* x      = (const float*)d_in[0];
    const float* tables = (const float*)d_in[1];
    float* out          = (float*)d_out;

    dim3 grid(N_POINTS / COLS_PER_BLOCK,   // 16 column tiles
              N_POINTS / ROWS_PER_BLOCK,   // 32 row tiles
              LEVELS);                     // 16 levels
    mrhe_kernel<<<grid, THREADS>>>(x, tables, out);
}

// round 15
// speedup vs baseline: 1.3657x; 1.3657x over previous
#include <cuda_runtime.h>
#include <cstdint>

#define N_POINTS   2048
#define LEVELS     16
#define TABLE_SIZE 524288
#define FEATS      8
#define OUT_COLS   (LEVELS * N_POINTS)   // 32768

#define ROWS_PER_BLOCK 64
#define COLS_PER_BLOCK 128
#define THREADS        256

__global__ __launch_bounds__(THREADS, 6)
void mrhe_kernel(const float* __restrict__ x,
                 const float* __restrict__ tables,
                 float* __restrict__ out)
{
    // out[i][j] = base[j] + fx[i]*dx[j] + fy[i]*dy[j] + fz[i]*dz[j]
    //   base = (f0+f2+f4)/3, dx = (f1-f0)/3, dy = (f3-f2)/3, dz = (f5-f4)/3
    // sB transposed: j-quad = one conflict-free LDS.128.
    // A tile: loaded ONCE into registers (lane l holds row r0+8*(l&7)),
    // broadcast per-iteration via __shfl_sync -> inner loop is stores-only
    // on the L1 path (4 wavefronts per 512B = the floor).
    __shared__ float  sB[4][COLS_PER_BLOCK];
    __shared__ float4 sA4[ROWS_PER_BLOCK];

    const int level = blockIdx.z;
    const int jt    = blockIdx.x * COLS_PER_BLOCK;
    const int it    = blockIdx.y * ROWS_PER_BLOCK;
    const float gridres = (float)(2 << level);        // 2^(level+1), exact
    const float* tab = tables + (size_t)level * TABLE_SIZE * FEATS;
    const int tid = threadIdx.x;
    const float inv3 = 1.0f / 3.0f;

    if (tid < COLS_PER_BLOCK) {
        // --- B tile: hash gather for column point j ---
        const int j = jt + tid;
        const float xj0 = x[j*3+0], xj1 = x[j*3+1], xj2 = x[j*3+2];
        const int hx = (int)floorf(xj0 * gridres);
        const int hy = (int)floorf(xj1 * gridres);
        const int hz = (int)floorf(xj2 * gridres);
        const int h  = (hx + hy + hz) & (TABLE_SIZE - 1); // sum < 2^19 == % T
        const float* row = tab + (size_t)h * FEATS;
        const float4 f03 = *(const float4*)(row);
        const float2 f45 = *(const float2*)(row + 4);
        sB[0][tid] = (f03.x + f03.z + f45.x) * inv3;
        sB[1][tid] = (f03.y - f03.x) * inv3;
        sB[2][tid] = (f03.w - f03.z) * inv3;
        sB[3][tid] = (f45.y - f45.x) * inv3;
    } else if (tid < COLS_PER_BLOCK + ROWS_PER_BLOCK) {
        // --- A tile: fract for row point i ---
        const int r = tid - COLS_PER_BLOCK;
        const int i = it + r;
        float sx = x[i*3+0] * gridres; sx -= floorf(sx);
        float sy = x[i*3+1] * gridres; sy -= floorf(sy);
        float sz = x[i*3+2] * gridres; sz -= floorf(sz);
        sA4[r] = make_float4(sx, sy, sz, 0.0f);
    }
    __syncthreads();

    const int jq  = tid & 31;   // j-quad within tile (32 quads = 128 cols)
    const int r0  = tid >> 5;   // warp id = row phase (0..7)
    const int lid = tid & 31;   // lane

    // 4 conflict-free LDS.128 pulls -> 16 registers of B state
    const float4 base = *(const float4*)&sB[0][jq * 4];
    const float4 dx   = *(const float4*)&sB[1][jq * 4];
    const float4 dy   = *(const float4*)&sB[2][jq * 4];
    const float4 dz   = *(const float4*)&sB[3][jq * 4];

    // A rows for this warp, register-resident: lane l holds row r0 + 8*(l&7).
    // (8 distinct addresses per warp, 4-lane broadcast each -> conflict-free.)
    const float4 myf = sA4[r0 + 8 * (lid & 7)];

    float* obase = out + (size_t)it * OUT_COLS
                       + (size_t)level * N_POINTS + jt + jq * 4;

#pragma unroll
    for (int rr = 0; rr < 8; rr++) {
        const int r = r0 + rr * 8;
        // Broadcast row rr's fract from lane rr — no L1 traffic.
        const float fx = __shfl_sync(0xffffffffu, myf.x, rr);
        const float fy = __shfl_sync(0xffffffffu, myf.y, rr);
        const float fz = __shfl_sync(0xffffffffu, myf.z, rr);
        float4 acc;
        acc.x = fmaf(fz, dz.x, fmaf(fy, dy.x, fmaf(fx, dx.x, base.x)));
        acc.y = fmaf(fz, dz.y, fmaf(fy, dy.y, fmaf(fx, dx.y, base.y)));
        acc.z = fmaf(fz, dz.z, fmaf(fy, dy.z, fmaf(fx, dx.z, base.z)));
        acc.w = fmaf(fz, dz.w, fmaf(fy, dy.w, fmaf(fx, dx.w, base.w)));
        // Write-once 256 MB stream: evict-first keeps table gathers L2-resident.
        __stcs((float4*)(obase + (size_t)r * OUT_COLS), acc);
    }
}

extern "C" void kernel_launch(void* const* d_in, const int* in_sizes, int n_in,
                              void* d_out, int out_size)
{
    const float* x      = (const float*)d_in[0];
    const float* tables = (const float*)d_in[1];
    float* out          = (float*)d_out;

    dim3 grid(N_POINTS / COLS_PER_BLOCK,   // 16 column tiles
              N_POINTS / ROWS_PER_BLOCK,   // 32 row tiles
              LEVELS);                     // 16 levels
    mrhe_kernel<<<grid, THREADS>>>(x, tables, out);
}

// round 16
// speedup vs baseline: 1.4880x; 1.0896x over previous
#include <cuda_runtime.h>
#include <cstdint>

#define N_POINTS   2048
#define LEVELS     16
#define TABLE_SIZE 524288
#define FEATS      8
#define OUT_COLS   (LEVELS * N_POINTS)   // 32768

#define ROWS_PER_BLOCK 64
#define COLS_PER_BLOCK 128
#define THREADS        256

__global__ __launch_bounds__(THREADS, 6)
void mrhe_kernel(const float* __restrict__ x,
                 const float* __restrict__ tables,
                 float* __restrict__ out)
{
    // out[i][j] = base[j] + fx[i]*dx[j] + fy[i]*dy[j] + fz[i]*dz[j]
    //   base = (f0+f2+f4)/3, dx = (f1-f0)/3, dy = (f3-f2)/3, dz = (f5-f4)/3
    // sB transposed: j-quad = one conflict-free LDS.128.
    // sA packed float4: one broadcast LDS.128 per row.
    __shared__ float  sB[4][COLS_PER_BLOCK];
    __shared__ float4 sA4[ROWS_PER_BLOCK];

    const int level = blockIdx.z;
    const int jt    = blockIdx.x * COLS_PER_BLOCK;
    const int it    = blockIdx.y * ROWS_PER_BLOCK;
    const float gridres = (float)(2 << level);        // 2^(level+1), exact
    const float* tab = tables + (size_t)level * TABLE_SIZE * FEATS;
    const int tid = threadIdx.x;
    const float inv3 = 1.0f / 3.0f;

    if (tid < COLS_PER_BLOCK) {
        // --- B tile: hash gather for column point j ---
        const int j = jt + tid;
        const float xj0 = x[j*3+0], xj1 = x[j*3+1], xj2 = x[j*3+2];
        const int hx = (int)floorf(xj0 * gridres);
        const int hy = (int)floorf(xj1 * gridres);
        const int hz = (int)floorf(xj2 * gridres);
        const int h  = (hx + hy + hz) & (TABLE_SIZE - 1); // sum < 2^19 == % T
        const float* row = tab + (size_t)h * FEATS;
        const float4 f03 = *(const float4*)(row);
        const float2 f45 = *(const float2*)(row + 4);
        sB[0][tid] = (f03.x + f03.z + f45.x) * inv3;
        sB[1][tid] = (f03.y - f03.x) * inv3;
        sB[2][tid] = (f03.w - f03.z) * inv3;
        sB[3][tid] = (f45.y - f45.x) * inv3;
    } else if (tid < COLS_PER_BLOCK + ROWS_PER_BLOCK) {
        // --- A tile: fract for row point i ---
        const int r = tid - COLS_PER_BLOCK;
        const int i = it + r;
        float sx = x[i*3+0] * gridres; sx -= floorf(sx);
        float sy = x[i*3+1] * gridres; sy -= floorf(sy);
        float sz = x[i*3+2] * gridres; sz -= floorf(sz);
        sA4[r] = make_float4(sx, sy, sz, 0.0f);
    }
    __syncthreads();

    const int jq = tid & 31;   // j-quad within tile (32 quads = 128 cols)
    const int r0 = tid >> 5;   // warp id = row phase (0..7)

    // 4 conflict-free LDS.128 pulls -> 16 registers of B state
    const float4 base = *(const float4*)&sB[0][jq * 4];
    const float4 dx   = *(const float4*)&sB[1][jq * 4];
    const float4 dy   = *(const float4*)&sB[2][jq * 4];
    const float4 dz   = *(const float4*)&sB[3][jq * 4];

    float* obase = out + (size_t)it * OUT_COLS
                       + (size_t)level * N_POINTS + jt + jq * 4;

#pragma unroll
    for (int rr = 0; rr < 8; rr++) {
        const int r = r0 + rr * 8;
        const float4 f = sA4[r];          // one broadcast LDS.128 per row
        float4 acc;
        acc.x = fmaf(f.z, dz.x, fmaf(f.y, dy.x, fmaf(f.x, dx.x, base.x)));
        acc.y = fmaf(f.z, dz.y, fmaf(f.y, dy.y, fmaf(f.x, dx.y, base.y)));
        acc.z = fmaf(f.z, dz.z, fmaf(f.y, dy.z, fmaf(f.x, dx.z, base.z)));
        acc.w = fmaf(f.z, dz.w, fmaf(f.y, dy.w, fmaf(f.x, dx.w, base.w)));
        // Write-once 256 MB stream: evict-first keeps table gathers L2-resident.
        __stcs((float4*)(obase + (size_t)r * OUT_COLS), acc);
    }
}

extern "C" void kernel_launch(void* const* d_in, const int* in_sizes, int n_in,
                              void* d_out, int out_size)
{
    const float* x      = (const float*)d_in[0];
    const float* tables = (const float*)d_in[1];
    float* out          = (float*)d_out;

    dim3 grid(N_POINTS / COLS_PER_BLOCK,   // 16 column tiles
              N_POINTS / ROWS_PER_BLOCK,   // 32 row tiles
              LEVELS);                     // 16 levels
    mrhe_kernel<<<grid, THREADS>>>(x, tables, out);
}